// round 16
// baseline (speedup 1.0000x reference)
#include <cuda_runtime.h>
#include <cuda_bf16.h>
#include <cuda_fp16.h>
#include <math.h>
#include <float.h>
#include <stdint.h>

#define Nn   50000
#define FIN  64
#define Hh   256
#define Ee   800000
#define Gg   2048
#define Ll   4
#define Tt   4
#define EPSc 1e-5f

#define MTILES ((Nn + 127) / 128)   // 391
#define Mpad   (MTILES * 128)       // 50048

// ---------------- scratch ----------------
__device__ __align__(16) __half g_hWh[(size_t)Mpad * Hh];   // fp16 message rows
__device__ float g_isd[Nn];
__device__ int   g_cnt[Nn];
__device__ int   g_off[Nn + 1];
__device__ int   g_cur[Nn];
__device__ int   g_csr[Ee];
__device__ float g_wgt[Ee];
__device__ int   g_part[64];
__device__ __align__(16) float g_pool[Gg * 2 * Hh];
__device__ __align__(16) float g_f1[Gg * Hh];
__device__ __align__(16) float g_f2[Gg * (Hh / 2)];
__device__ __align__(16) __nv_bfloat16 g_Ahi[(size_t)Mpad * Hh];
__device__ __align__(16) __nv_bfloat16 g_Alo[(size_t)Mpad * Hh];
__device__ __align__(16) __nv_bfloat16 g_Bhi[Ll * Hh * Hh];
__device__ __align__(16) __nv_bfloat16 g_Blo[Ll * Hh * Hh];
__device__ __align__(16) __nv_bfloat16 g_Xhi[(size_t)Mpad * FIN];
__device__ __align__(16) __nv_bfloat16 g_Xlo[(size_t)Mpad * FIN];
__device__ __align__(16) __nv_bfloat16 g_PBhi[FIN * Hh];
__device__ __align__(16) __nv_bfloat16 g_PBlo[FIN * Hh];

// ---------------- asm helpers ----------------
__device__ __forceinline__ uint32_t smem_u32(const void* p) {
    uint32_t a;
    asm("{ .reg .u64 t; cvta.to.shared.u64 t, %1; cvt.u32.u64 %0, t; }" : "=r"(a) : "l"(p));
    return a;
}
#define CPA(dst, src) \
    asm volatile("cp.async.cg.shared.global [%0], [%1], 16;" :: "r"(dst), "l"(src) : "memory")
#define LDSM4(r, addr) \
    asm volatile("ldmatrix.sync.aligned.m8n8.x4.shared.b16 {%0,%1,%2,%3}, [%4];" \
        : "=r"((r)[0]), "=r"((r)[1]), "=r"((r)[2]), "=r"((r)[3]) : "r"(addr))
#define LDSM4T(r, addr) \
    asm volatile("ldmatrix.sync.aligned.m8n8.x4.trans.shared.b16 {%0,%1,%2,%3}, [%4];" \
        : "=r"((r)[0]), "=r"((r)[1]), "=r"((r)[2]), "=r"((r)[3]) : "r"(addr))
#define MMA16816(c, a, b) \
    asm volatile("mma.sync.aligned.m16n8k16.row.col.f32.bf16.bf16.f32 " \
        "{%0,%1,%2,%3}, {%4,%5,%6,%7}, {%8,%9}, {%0,%1,%2,%3};" \
        : "+f"((c)[0]), "+f"((c)[1]), "+f"((c)[2]), "+f"((c)[3]) \
        : "r"((a)[0]), "r"((a)[1]), "r"((a)[2]), "r"((a)[3]), "r"((b)[0]), "r"((b)[1]))

__device__ __forceinline__ uint32_t pack_hi2(float x, float y) {
    __nv_bfloat16 a = __float2bfloat16(x), b = __float2bfloat16(y);
    return ((uint32_t)*(uint16_t*)&b << 16) | *(uint16_t*)&a;
}
__device__ __forceinline__ uint32_t pack_lo2(float x, float y) {
    __nv_bfloat16 a = __float2bfloat16(x), b = __float2bfloat16(y);
    __nv_bfloat16 la = __float2bfloat16(x - __bfloat162float(a));
    __nv_bfloat16 lb = __float2bfloat16(y - __bfloat162float(b));
    return ((uint32_t)*(uint16_t*)&lb << 16) | *(uint16_t*)&la;
}
__device__ __forceinline__ float2 unpack2(uint32_t hi, uint32_t lo) {
    __nv_bfloat162 h = *(__nv_bfloat162*)&hi;
    __nv_bfloat162 l = *(__nv_bfloat162*)&lo;
    float2 r;
    r.x = __bfloat162float(h.x) + __bfloat162float(l.x);
    r.y = __bfloat162float(h.y) + __bfloat162float(l.y);
    return r;
}
__device__ __forceinline__ void fma4(float4& acc, uint2 q, float w) {
    float2 a = __half22float2(*(__half2*)&q.x);
    float2 b = __half22float2(*(__half2*)&q.y);
    acc.x = fmaf(a.x, w, acc.x);
    acc.y = fmaf(a.y, w, acc.y);
    acc.z = fmaf(b.x, w, acc.z);
    acc.w = fmaf(b.y, w, acc.w);
}

// ---------------- setup kernels ----------------
__global__ void k_split_x(const float* __restrict__ x) {
    int idx = blockIdx.x * blockDim.x + threadIdx.x;
    if (idx < Nn) g_cnt[idx] = 0;
    if (idx >= Nn * FIN / 4) return;
    float4 v = *(const float4*)&x[idx * 4];
    uint2 hv, lv;
    hv.x = pack_hi2(v.x, v.y); hv.y = pack_hi2(v.z, v.w);
    lv.x = pack_lo2(v.x, v.y); lv.y = pack_lo2(v.z, v.w);
    *(uint2*)&g_Xhi[idx * 4] = hv;
    *(uint2*)&g_Xlo[idx * 4] = lv;
}
__global__ void k_wsplit(const float* __restrict__ convW, const float* __restrict__ projW) {
    int idx = blockIdx.x * blockDim.x + threadIdx.x;
    if (idx < Ll * Hh * Hh) {
        float w = convW[idx];
        __nv_bfloat16 hi = __float2bfloat16(w);
        g_Bhi[idx] = hi;
        g_Blo[idx] = __float2bfloat16(w - __bfloat162float(hi));
    } else if (idx < Ll * Hh * Hh + FIN * Hh) {
        int j = idx - Ll * Hh * Hh;
        float w = projW[j];
        __nv_bfloat16 hi = __float2bfloat16(w);
        g_PBhi[j] = hi;
        g_PBlo[j] = __float2bfloat16(w - __bfloat162float(hi));
    }
}
__global__ void k_count_edges(const int* __restrict__ ei) {
    int i = blockIdx.x * blockDim.x + threadIdx.x;
    if (i >= Ee / 4) return;
    int4 d4 = *(const int4*)&ei[Ee + i * 4];
    atomicAdd(&g_cnt[d4.x], 1);
    atomicAdd(&g_cnt[d4.y], 1);
    atomicAdd(&g_cnt[d4.z], 1);
    atomicAdd(&g_cnt[d4.w], 1);
}
__global__ void k_scan_block() {
    __shared__ int s[1024];
    int gid = blockIdx.x * 1024 + threadIdx.x;
    int v = (gid < Nn) ? g_cnt[gid] : 0;
    s[threadIdx.x] = v;
    for (int d = 1; d < 1024; d <<= 1) {
        __syncthreads();
        int t = (threadIdx.x >= d) ? s[threadIdx.x - d] : 0;
        __syncthreads();
        s[threadIdx.x] += t;
    }
    __syncthreads();
    if (gid < Nn) g_off[gid] = s[threadIdx.x] - v;
    if (threadIdx.x == 1023) g_part[blockIdx.x] = s[1023];
}
__global__ void k_scan_add() {
    __shared__ int base;
    if (threadIdx.x == 0) {
        int acc = 0;
        for (int i = 0; i < blockIdx.x; i++) acc += g_part[i];
        base = acc;
    }
    __syncthreads();
    int gid = blockIdx.x * 1024 + threadIdx.x;
    if (gid < Nn) {
        int v = g_off[gid] + base;
        g_off[gid] = v;
        g_cur[gid] = v;
        g_isd[gid] = rsqrtf(1.0f + (float)g_cnt[gid]);
    }
    if (gid == 0) g_off[Nn] = Ee;
}
__global__ void k_csr_fill(const int* __restrict__ ei) {
    int i = blockIdx.x * blockDim.x + threadIdx.x;
    if (i >= Ee / 4) return;
    int4 s4 = *(const int4*)&ei[i * 4];
    int4 d4 = *(const int4*)&ei[Ee + i * 4];
    int p0 = atomicAdd(&g_cur[d4.x], 1);
    int p1 = atomicAdd(&g_cur[d4.y], 1);
    int p2 = atomicAdd(&g_cur[d4.z], 1);
    int p3 = atomicAdd(&g_cur[d4.w], 1);
    g_csr[p0] = s4.x; g_wgt[p0] = g_isd[s4.x] * g_isd[d4.x];
    g_csr[p1] = s4.y; g_wgt[p1] = g_isd[s4.y] * g_isd[d4.y];
    g_csr[p2] = s4.z; g_wgt[p2] = g_isd[s4.z] * g_isd[d4.z];
    g_csr[p3] = s4.w; g_wgt[p3] = g_isd[s4.w] * g_isd[d4.w];
}

// ---------------- bf16x3 mma.sync GEMM, 4-slot K16 cp.async ring (champion form) ----------------
#define SLOT   20992
#define ALO_O  6144
#define BHI_O  12288
#define BLO_O  16640
#define SMEM_G (4 * SLOT)   // 83968

template<int KSTAGES, int MODE>
__global__ __launch_bounds__(256, 2) void k_gemm_mma(int layer, const float* __restrict__ bias) {
    extern __shared__ __align__(16) unsigned char smraw[];
    const int tid = threadIdx.x, lane = tid & 31, wid = tid >> 5;
    const int warp_m = wid & 3, warp_n = wid >> 2;
    const int m0 = blockIdx.x * 128, n0 = blockIdx.y * 128;
    const uint32_t sb = smem_u32(smraw);
    const int kdim = KSTAGES * 16;

    const __nv_bfloat16* Ah = (MODE == 0) ? g_Ahi : g_Xhi;
    const __nv_bfloat16* Al = (MODE == 0) ? g_Alo : g_Xlo;
    const __nv_bfloat16* Bh = (MODE == 0) ? g_Bhi + (size_t)layer * Hh * Hh : g_PBhi;
    const __nv_bfloat16* Bl = (MODE == 0) ? g_Blo + (size_t)layer * Hh * Hh : g_PBlo;

    const int a_r = tid >> 1, a_c = tid & 1;
    const int b_r = tid >> 4, b_c = tid & 15;

#define LOAD_STAGE(slotbase, kt) do { \
        int k0 = (kt) * 16; \
        CPA((slotbase) + a_r * 48 + a_c * 16, \
            Ah + (size_t)(m0 + a_r) * kdim + k0 + a_c * 8); \
        CPA((slotbase) + ALO_O + a_r * 48 + a_c * 16, \
            Al + (size_t)(m0 + a_r) * kdim + k0 + a_c * 8); \
        CPA((slotbase) + BHI_O + b_r * 272 + b_c * 16, \
            Bh + (size_t)(k0 + b_r) * Hh + n0 + b_c * 8); \
        CPA((slotbase) + BLO_O + b_r * 272 + b_c * 16, \
            Bl + (size_t)(k0 + b_r) * Hh + n0 + b_c * 8); \
        asm volatile("cp.async.commit_group;" ::: "memory"); \
    } while (0)

    float acc[2][8][4];
    #pragma unroll
    for (int i = 0; i < 2; i++)
        #pragma unroll
        for (int j = 0; j < 8; j++)
            #pragma unroll
            for (int q = 0; q < 4; q++) acc[i][j][q] = 0.f;

    const uint32_t aoff = sb + (warp_m * 32 + (lane & 15)) * 48 + (lane >> 4) * 16;
    const uint32_t boff = sb + BHI_O + (lane & 15) * 272 + (warp_n * 8 + (lane >> 4)) * 16;

    LOAD_STAGE(sb, 0);
    LOAD_STAGE(sb + SLOT, 1);
    LOAD_STAGE(sb + 2 * SLOT, 2);

    #pragma unroll
    for (int kt = 0; kt < KSTAGES; kt++) {
        const uint32_t s = (kt & 3) * SLOT;
        asm volatile("cp.async.wait_group 2;" ::: "memory");
        __syncthreads();
        if (kt + 3 < KSTAGES) {
            LOAD_STAGE(sb + ((kt + 3) & 3) * SLOT, kt + 3);
        } else {
            asm volatile("cp.async.commit_group;" ::: "memory");
        }

        uint32_t ah[2][4], al[2][4], bh[4][4], bl[4][4];
        #pragma unroll
        for (int mt = 0; mt < 2; mt++) {
            LDSM4(ah[mt], aoff + s + mt * 768);
            LDSM4(al[mt], aoff + s + ALO_O + mt * 768);
        }
        #pragma unroll
        for (int nt = 0; nt < 4; nt++) {
            LDSM4T(bh[nt], boff + s + nt * 32);
            LDSM4T(bl[nt], boff + s + (BLO_O - BHI_O) + nt * 32);
        }
        #pragma unroll
        for (int mt = 0; mt < 2; mt++)
            #pragma unroll
            for (int nt = 0; nt < 4; nt++)
                #pragma unroll
                for (int nb = 0; nb < 2; nb++) {
                    float* c = acc[mt][nt * 2 + nb];
                    MMA16816(c, ah[mt], &bh[nt][nb * 2]);
                    MMA16816(c, ah[mt], &bl[nt][nb * 2]);
                    MMA16816(c, al[mt], &bh[nt][nb * 2]);
                }
    }
#undef LOAD_STAGE

    #pragma unroll
    for (int mt = 0; mt < 2; mt++) {
        int rbase = m0 + warp_m * 32 + mt * 16 + (lane >> 2);
        #pragma unroll
        for (int half = 0; half < 2; half++) {
            int r = rbase + half * 8;
            #pragma unroll
            for (int j = 0; j < 8; j++) {
                int n = n0 + warp_n * 64 + j * 8 + (lane & 3) * 2;
                float vx = acc[mt][j][half * 2 + 0];
                float vy = acc[mt][j][half * 2 + 1];
                if (MODE == 0) {
                    __half2 hv = __floats2half2_rn(vx, vy);
                    *(__half2*)&g_hWh[(size_t)r * Hh + n] = hv;
                } else if (r < Nn) {
                    float2 bi = *(const float2*)&bias[n];
                    vx = fmaxf(vx + bi.x, 0.f);
                    vy = fmaxf(vy + bi.y, 0.f);
                    *(uint32_t*)&g_Ahi[(size_t)r * Hh + n] = pack_hi2(vx, vy);
                    *(uint32_t*)&g_Alo[(size_t)r * Hh + n] = pack_lo2(vx, vy);
                }
            }
        }
    }
}

// ---------------- SIMT SGEMM (head only) ----------------
__global__ void k_sgemm(const float* __restrict__ B, const float* __restrict__ bias,
                        int M, int N, int K, int sel) {
    const float* A = (sel == 2) ? g_pool : g_f1;
    float*       C = (sel == 2) ? g_f1  : g_f2;

    __shared__ float As[16][64];
    __shared__ float Bs[16][68];

    int tid = threadIdx.x;
    int m0 = blockIdx.y * 64, n0 = blockIdx.x * 64;
    int tr = tid >> 4, tc = tid & 15;
    int arow = tid >> 2, aq = (tid & 3) * 4;
    int brow = tid >> 4, bq = (tid & 15) * 4;

    float acc[4][4];
    #pragma unroll
    for (int i = 0; i < 4; i++)
        #pragma unroll
        for (int j = 0; j < 4; j++) acc[i][j] = 0.f;

    for (int k0 = 0; k0 < K; k0 += 16) {
        float4 av;
        if (m0 + arow < M)
            av = *reinterpret_cast<const float4*>(&A[(size_t)(m0 + arow) * K + k0 + aq]);
        else
            av = make_float4(0.f, 0.f, 0.f, 0.f);
        As[aq + 0][arow] = av.x;
        As[aq + 1][arow] = av.y;
        As[aq + 2][arow] = av.z;
        As[aq + 3][arow] = av.w;

        float4 bv = *reinterpret_cast<const float4*>(&B[(size_t)(k0 + brow) * N + n0 + bq]);
        Bs[brow][bq + 0] = bv.x;
        Bs[brow][bq + 1] = bv.y;
        Bs[brow][bq + 2] = bv.z;
        Bs[brow][bq + 3] = bv.w;
        __syncthreads();

        #pragma unroll
        for (int k = 0; k < 16; k++) {
            float arr[4], br[4];
            #pragma unroll
            for (int i = 0; i < 4; i++) arr[i] = As[k][tr * 4 + i];
            #pragma unroll
            for (int j = 0; j < 4; j++) br[j] = Bs[k][tc * 4 + j];
            #pragma unroll
            for (int i = 0; i < 4; i++)
                #pragma unroll
                for (int j = 0; j < 4; j++) acc[i][j] = fmaf(arr[i], br[j], acc[i][j]);
        }
        __syncthreads();
    }

    #pragma unroll
    for (int i = 0; i < 4; i++) {
        int m = m0 + tr * 4 + i;
        if (m >= M) continue;
        #pragma unroll
        for (int j = 0; j < 4; j++) {
            int n = n0 + tc * 4 + j;
            float v = fmaxf(acc[i][j] + bias[n], 0.f);
            C[(size_t)m * N + n] = v;
        }
    }
}

// ---------------- fused aggregation: smem-staged edge meta, champion gather loop ----------------
__global__ __launch_bounds__(256) void k_agg_fused(
        const float* __restrict__ bias, const float* __restrict__ gamma,
        const float* __restrict__ beta, const float* __restrict__ mean,
        const float* __restrict__ var) {
    __shared__ int   s_csr[4][64];
    __shared__ float s_wgt[4][64];
    __shared__ int   s_mx;

    int slot = threadIdx.x >> 6;          // node slot 0..3
    int lt   = threadIdx.x & 63;          // lane within node group
    int v = blockIdx.x * 4 + slot;
    bool valid = (v < Nn);
    int c = lt * 4;

    int j0 = 0, j1 = 0;
    float4 acc = make_float4(0.f, 0.f, 0.f, 0.f);
    if (valid) {
        j0 = g_off[v];
        j1 = g_off[v + 1];
        float idv = g_isd[v];
        float ws = idv * idv;
        uint2 sr = *(const uint2*)&g_hWh[(size_t)v * Hh + c];
        float2 s0 = __half22float2(*(__half2*)&sr.x);
        float2 s1 = __half22float2(*(__half2*)&sr.y);
        acc = make_float4(s0.x * ws, s0.y * ws, s1.x * ws, s1.y * ws);
    }

    if (threadIdx.x == 0) s_mx = 0;
    __syncthreads();
    if (valid && lt == 0) atomicMax(&s_mx, (j1 - j0 + 63) >> 6);
    __syncthreads();
    const int mx = s_mx;

    for (int ch = 0; ch < mx; ch++) {
        int base = j0 + (ch << 6);
        if (valid) {
            int idx = base + lt;
            if (idx < j1) {
                s_csr[slot][lt] = g_csr[idx];
                s_wgt[slot][lt] = g_wgt[idx];
            }
        }
        __syncthreads();

        int len = 0;
        if (valid) { len = j1 - base; len = (len < 0) ? 0 : (len > 64 ? 64 : len); }
        int jj = 0;
        for (; jj + 4 <= len; jj += 4) {
            int u0 = s_csr[slot][jj],     u1 = s_csr[slot][jj + 1];
            int u2 = s_csr[slot][jj + 2], u3 = s_csr[slot][jj + 3];
            float w0 = s_wgt[slot][jj],     w1 = s_wgt[slot][jj + 1];
            float w2 = s_wgt[slot][jj + 2], w3 = s_wgt[slot][jj + 3];
            uint2 q0 = *(const uint2*)&g_hWh[(size_t)u0 * Hh + c];
            uint2 q1 = *(const uint2*)&g_hWh[(size_t)u1 * Hh + c];
            uint2 q2 = *(const uint2*)&g_hWh[(size_t)u2 * Hh + c];
            uint2 q3 = *(const uint2*)&g_hWh[(size_t)u3 * Hh + c];
            fma4(acc, q0, w0);
            fma4(acc, q1, w1);
            fma4(acc, q2, w2);
            fma4(acc, q3, w3);
        }
        for (; jj < len; jj++) {
            int u = s_csr[slot][jj];
            float w = s_wgt[slot][jj];
            uint2 q = *(const uint2*)&g_hWh[(size_t)u * Hh + c];
            fma4(acc, q, w);
        }
        __syncthreads();
    }

    if (!valid) return;

    float4 bi = *(const float4*)&bias[c];
    float4 ga = *(const float4*)&gamma[c];
    float4 be = *(const float4*)&beta[c];
    float4 me = *(const float4*)&mean[c];
    float4 va = *(const float4*)&var[c];

    uint2 rh = *(const uint2*)&g_Ahi[(size_t)v * Hh + c];
    uint2 rl = *(const uint2*)&g_Alo[(size_t)v * Hh + c];
    float2 r01 = unpack2(rh.x, rl.x);
    float2 r23 = unpack2(rh.y, rl.y);

    float4 o;
    o.x = fmaxf((acc.x + bi.x - me.x) * (ga.x * rsqrtf(va.x + EPSc)) + be.x, 0.f) + r01.x;
    o.y = fmaxf((acc.y + bi.y - me.y) * (ga.y * rsqrtf(va.y + EPSc)) + be.y, 0.f) + r01.y;
    o.z = fmaxf((acc.z + bi.z - me.z) * (ga.z * rsqrtf(va.z + EPSc)) + be.z, 0.f) + r23.x;
    o.w = fmaxf((acc.w + bi.w - me.w) * (ga.w * rsqrtf(va.w + EPSc)) + be.w, 0.f) + r23.y;

    uint2 hv, lv;
    hv.x = pack_hi2(o.x, o.y); hv.y = pack_hi2(o.z, o.w);
    lv.x = pack_lo2(o.x, o.y); lv.y = pack_lo2(o.z, o.w);
    *(uint2*)&g_Ahi[(size_t)v * Hh + c] = hv;
    *(uint2*)&g_Alo[(size_t)v * Hh + c] = lv;
}

// ---------------- pooling: 2 graphs/block, 2 features/thread, packed loads ----------------
__global__ void k_pool(const int* __restrict__ batch) {
    __shared__ int sbb[3];
    int grp_base = blockIdx.x * 2;
    int sub = threadIdx.x >> 7;
    int t2 = (threadIdx.x & 127) * 2;
    if (threadIdx.x < 3) {
        int key = grp_base + threadIdx.x;
        int lo = 0, hi = Nn;
        while (lo < hi) {
            int mid = (lo + hi) >> 1;
            if (batch[mid] < key) lo = mid + 1; else hi = mid;
        }
        sbb[threadIdx.x] = lo;
    }
    __syncthreads();
    int grp = grp_base + sub;
    int s = sbb[sub], e = sbb[sub + 1];
    float2 sum = {0.f, 0.f}, mx = {-FLT_MAX, -FLT_MAX};
    for (int i = s; i < e; i++) {
        uint32_t hi = *(const uint32_t*)&g_Ahi[(size_t)i * Hh + t2];
        uint32_t lo = *(const uint32_t*)&g_Alo[(size_t)i * Hh + t2];
        float2 v = unpack2(hi, lo);
        sum.x += v.x; sum.y += v.y;
        mx.x = fmaxf(mx.x, v.x); mx.y = fmaxf(mx.y, v.y);
    }
    float cinv = 1.f / fmaxf((float)(e - s), 1.f);
    float* dst = &g_pool[(size_t)grp * (2 * Hh)];
    dst[t2]     = sum.x * cinv;
    dst[t2 + 1] = sum.y * cinv;
    dst[Hh + t2]     = mx.x;
    dst[Hh + t2 + 1] = mx.y;
}

// ---------------- final tiny GEMM ----------------
__global__ void k_head3(const float* __restrict__ W, const float* __restrict__ b,
                        float* __restrict__ out) {
    int idx = blockIdx.x * blockDim.x + threadIdx.x;
    if (idx >= Gg * Tt) return;
    int r = idx >> 2, c = idx & 3;
    float acc = b[c];
    const float* row = &g_f2[(size_t)r * 128];
    #pragma unroll 8
    for (int k = 0; k < 128; k++) acc = fmaf(row[k], W[k * 4 + c], acc);
    out[idx] = acc;
}

// ---------------- launch ----------------
extern "C" void kernel_launch(void* const* d_in, const int* in_sizes, int n_in,
                              void* d_out, int out_size) {
    const float* x     = (const float*)d_in[0];
    const int*   ei    = (const int*)d_in[1];
    const int*   batch = (const int*)d_in[2];
    const float* projW = (const float*)d_in[3];
    const float* projb = (const float*)d_in[4];
    const float* convW = (const float*)d_in[5];
    const float* convb = (const float*)d_in[6];
    const float* gamma = (const float*)d_in[7];
    const float* beta  = (const float*)d_in[8];
    const float* mean  = (const float*)d_in[9];
    const float* var   = (const float*)d_in[10];
    const float* W1 = (const float*)d_in[11];
    const float* b1 = (const float*)d_in[12];
    const float* W2 = (const float*)d_in[13];
    const float* b2 = (const float*)d_in[14];
    const float* W3 = (const float*)d_in[15];
    const float* b3 = (const float*)d_in[16];
    float* out = (float*)d_out;

    const int SCAN_B = (Nn + 1023) / 1024;

    cudaFuncSetAttribute(k_gemm_mma<16, 0>, cudaFuncAttributeMaxDynamicSharedMemorySize, SMEM_G);
    cudaFuncSetAttribute(k_gemm_mma<4, 1>, cudaFuncAttributeMaxDynamicSharedMemorySize, SMEM_G);

    // 0-2: splits + proj
    k_split_x  <<<(Nn * FIN / 4 + 255) / 256, 256>>>(x);
    k_wsplit   <<<(Ll * Hh * Hh + FIN * Hh + 255) / 256, 256>>>(convW, projW);
    k_gemm_mma<4, 1><<<dim3(MTILES, 2), 256, SMEM_G>>>(0, projb);

    // 3: conv GEMM layer 0 — in ncu window
    k_gemm_mma<16, 0><<<dim3(MTILES, 2), 256, SMEM_G>>>(0, nullptr);

    // CSR build
    k_count_edges<<<(Ee / 4 + 255) / 256, 256>>>(ei);
    k_scan_block <<<SCAN_B, 1024>>>();
    k_scan_add   <<<SCAN_B, 1024>>>();
    k_csr_fill   <<<(Ee / 4 + 255) / 256, 256>>>(ei);

    // layer 0 aggregation, then layers 1..3
    k_agg_fused<<<(Nn + 3) / 4, 256>>>(convb, gamma, beta, mean, var);
    for (int l = 1; l < Ll; l++) {
        k_gemm_mma<16, 0><<<dim3(MTILES, 2), 256, SMEM_G>>>(l, nullptr);
        k_agg_fused<<<(Nn + 3) / 4, 256>>>(convb + l * Hh, gamma + l * Hh, beta + l * Hh,
                                           mean + l * Hh, var + l * Hh);
    }

    // pooling + head
    k_pool<<<Gg / 2, 256>>>(batch);
    k_sgemm<<<dim3(Hh / 64, Gg / 64), 256>>>(W1, b1, Gg, Hh, 2 * Hh, 2);
    k_sgemm<<<dim3((Hh / 2) / 64, Gg / 64), 256>>>(W2, b2, Gg, Hh / 2, Hh, 3);
    k_head3<<<(Gg * Tt + 255) / 256, 256>>>(W3, b3, out);
}

// round 17
// speedup vs baseline: 1.2016x; 1.2016x over previous
#include <cuda_runtime.h>
#include <cuda_fp16.h>
#include <math.h>
#include <float.h>
#include <stdint.h>

#define Nn   50000
#define FIN  64
#define Hh   256
#define Ee   800000
#define Gg   2048
#define Ll   4
#define Tt   4
#define EPSc 1e-5f

#define MTILES ((Nn + 127) / 128)   // 391
#define Mpad   (MTILES * 128)       // 50048

// ---------------- scratch ----------------
__device__ __align__(16) __half g_hWh[(size_t)Mpad * Hh];   // fp16 message rows
__device__ float g_isd[Nn];
__device__ int   g_cnt[Nn];
__device__ int   g_off[Nn + 1];
__device__ int   g_cur[Nn];
__device__ int   g_csr[Ee];
__device__ float g_wgt[Ee];
__device__ int   g_part[64];
__device__ __align__(16) float g_pool[Gg * 2 * Hh];
__device__ __align__(16) float g_f1[Gg * Hh];
__device__ __align__(16) float g_f2[Gg * (Hh / 2)];
// h stored as fp16 hi/lo pair (reconstruction error ~2^-22)
__device__ __align__(16) __half g_Ah[(size_t)Mpad * Hh];
__device__ __align__(16) __half g_Al[(size_t)Mpad * Hh];
__device__ __align__(16) __half g_Bh[Ll * Hh * Hh];
__device__ __align__(16) __half g_Bl[Ll * Hh * Hh];
__device__ __align__(16) __half g_Xh[(size_t)Mpad * FIN];
__device__ __align__(16) __half g_Xl[(size_t)Mpad * FIN];
__device__ __align__(16) __half g_PBh[FIN * Hh];
__device__ __align__(16) __half g_PBl[FIN * Hh];

// ---------------- asm helpers ----------------
__device__ __forceinline__ uint32_t smem_u32(const void* p) {
    uint32_t a;
    asm("{ .reg .u64 t; cvta.to.shared.u64 t, %1; cvt.u32.u64 %0, t; }" : "=r"(a) : "l"(p));
    return a;
}
#define CPA(dst, src) \
    asm volatile("cp.async.cg.shared.global [%0], [%1], 16;" :: "r"(dst), "l"(src) : "memory")
#define LDSM4(r, addr) \
    asm volatile("ldmatrix.sync.aligned.m8n8.x4.shared.b16 {%0,%1,%2,%3}, [%4];" \
        : "=r"((r)[0]), "=r"((r)[1]), "=r"((r)[2]), "=r"((r)[3]) : "r"(addr))
#define LDSM4T(r, addr) \
    asm volatile("ldmatrix.sync.aligned.m8n8.x4.trans.shared.b16 {%0,%1,%2,%3}, [%4];" \
        : "=r"((r)[0]), "=r"((r)[1]), "=r"((r)[2]), "=r"((r)[3]) : "r"(addr))
#define MMAF16(c, a, b) \
    asm volatile("mma.sync.aligned.m16n8k16.row.col.f32.f16.f16.f32 " \
        "{%0,%1,%2,%3}, {%4,%5,%6,%7}, {%8,%9}, {%0,%1,%2,%3};" \
        : "+f"((c)[0]), "+f"((c)[1]), "+f"((c)[2]), "+f"((c)[3]) \
        : "r"((a)[0]), "r"((a)[1]), "r"((a)[2]), "r"((a)[3]), "r"((b)[0]), "r"((b)[1]))

__device__ __forceinline__ uint32_t packh2(float x, float y) {
    __half2 h = __floats2half2_rn(x, y);
    return *(uint32_t*)&h;
}
__device__ __forceinline__ uint32_t packl2(float x, float y) {
    __half hx = __float2half_rn(x), hy = __float2half_rn(y);
    __half lx = __float2half_rn(x - __half2float(hx));
    __half ly = __float2half_rn(y - __half2float(hy));
    __half2 l = __halves2half2(lx, ly);
    return *(uint32_t*)&l;
}
__device__ __forceinline__ float2 unpack2(uint32_t hi, uint32_t lo) {
    float2 a = __half22float2(*(__half2*)&hi);
    float2 b = __half22float2(*(__half2*)&lo);
    float2 r;
    r.x = a.x + b.x;
    r.y = a.y + b.y;
    return r;
}
__device__ __forceinline__ void fma4(float4& acc, uint2 q, float w) {
    float2 a = __half22float2(*(__half2*)&q.x);
    float2 b = __half22float2(*(__half2*)&q.y);
    acc.x = fmaf(a.x, w, acc.x);
    acc.y = fmaf(a.y, w, acc.y);
    acc.z = fmaf(b.x, w, acc.z);
    acc.w = fmaf(b.y, w, acc.w);
}

// ---------------- setup kernels ----------------
__global__ void k_split_x(const float* __restrict__ x) {
    int idx = blockIdx.x * blockDim.x + threadIdx.x;
    if (idx < Nn) g_cnt[idx] = 0;
    if (idx >= Nn * FIN / 4) return;
    float4 v = *(const float4*)&x[idx * 4];
    uint2 hv, lv;
    hv.x = packh2(v.x, v.y); hv.y = packh2(v.z, v.w);
    lv.x = packl2(v.x, v.y); lv.y = packl2(v.z, v.w);
    *(uint2*)&g_Xh[idx * 4] = hv;
    *(uint2*)&g_Xl[idx * 4] = lv;
}
__global__ void k_wsplit(const float* __restrict__ convW, const float* __restrict__ projW) {
    int idx = blockIdx.x * blockDim.x + threadIdx.x;
    if (idx < Ll * Hh * Hh) {
        float w = convW[idx];
        __half hi = __float2half_rn(w);
        g_Bh[idx] = hi;
        g_Bl[idx] = __float2half_rn(w - __half2float(hi));
    } else if (idx < Ll * Hh * Hh + FIN * Hh) {
        int j = idx - Ll * Hh * Hh;
        float w = projW[j];
        __half hi = __float2half_rn(w);
        g_PBh[j] = hi;
        g_PBl[j] = __float2half_rn(w - __half2float(hi));
    }
}
__global__ void k_count_edges(const int* __restrict__ ei) {
    int i = blockIdx.x * blockDim.x + threadIdx.x;
    if (i >= Ee / 4) return;
    int4 d4 = *(const int4*)&ei[Ee + i * 4];
    atomicAdd(&g_cnt[d4.x], 1);
    atomicAdd(&g_cnt[d4.y], 1);
    atomicAdd(&g_cnt[d4.z], 1);
    atomicAdd(&g_cnt[d4.w], 1);
}
__global__ void k_scan_block() {
    __shared__ int s[1024];
    int gid = blockIdx.x * 1024 + threadIdx.x;
    int v = (gid < Nn) ? g_cnt[gid] : 0;
    s[threadIdx.x] = v;
    for (int d = 1; d < 1024; d <<= 1) {
        __syncthreads();
        int t = (threadIdx.x >= d) ? s[threadIdx.x - d] : 0;
        __syncthreads();
        s[threadIdx.x] += t;
    }
    __syncthreads();
    if (gid < Nn) g_off[gid] = s[threadIdx.x] - v;
    if (threadIdx.x == 1023) g_part[blockIdx.x] = s[1023];
}
__global__ void k_scan_add() {
    __shared__ int base;
    if (threadIdx.x == 0) {
        int acc = 0;
        for (int i = 0; i < blockIdx.x; i++) acc += g_part[i];
        base = acc;
    }
    __syncthreads();
    int gid = blockIdx.x * 1024 + threadIdx.x;
    if (gid < Nn) {
        int v = g_off[gid] + base;
        g_off[gid] = v;
        g_cur[gid] = v;
        g_isd[gid] = rsqrtf(1.0f + (float)g_cnt[gid]);
    }
    if (gid == 0) g_off[Nn] = Ee;
}
__global__ void k_csr_fill(const int* __restrict__ ei) {
    int i = blockIdx.x * blockDim.x + threadIdx.x;
    if (i >= Ee / 4) return;
    int4 s4 = *(const int4*)&ei[i * 4];
    int4 d4 = *(const int4*)&ei[Ee + i * 4];
    int p0 = atomicAdd(&g_cur[d4.x], 1);
    int p1 = atomicAdd(&g_cur[d4.y], 1);
    int p2 = atomicAdd(&g_cur[d4.z], 1);
    int p3 = atomicAdd(&g_cur[d4.w], 1);
    g_csr[p0] = s4.x; g_wgt[p0] = g_isd[s4.x] * g_isd[d4.x];
    g_csr[p1] = s4.y; g_wgt[p1] = g_isd[s4.y] * g_isd[d4.y];
    g_csr[p2] = s4.z; g_wgt[p2] = g_isd[s4.z] * g_isd[d4.z];
    g_csr[p3] = s4.w; g_wgt[p3] = g_isd[s4.w] * g_isd[d4.w];
}

// ---------------- fp16 mma GEMM, 4-slot K16 cp.async ring ----------------
// MODE 0 (conv): A = g_Ah (fp16 single), B = g_Bh/g_Bl + layer, 2 passes, C -> g_hWh
// MODE 1 (proj): A = g_Xh/g_Xl (pair),   B = g_PBh/g_PBl,      3 passes, C -> h fp16 pair
// Slot MODE0 (14848): A 6144 | Bh 4352 | Bl 4352
// Slot MODE1 (20992): A 6144 | Al 6144 | Bh 4352 | Bl 4352
template<int KSTAGES, int MODE>
__global__ __launch_bounds__(256, 2) void k_gemm_mma(int layer, const float* __restrict__ bias) {
    constexpr int SLOT  = (MODE == 0) ? 14848 : 20992;
    constexpr int ALO_O = 6144;                       // MODE 1 only
    constexpr int BH_O  = (MODE == 0) ? 6144 : 12288;
    constexpr int BL_O  = BH_O + 4352;

    extern __shared__ __align__(16) unsigned char smraw[];
    const int tid = threadIdx.x, lane = tid & 31, wid = tid >> 5;
    const int warp_m = wid & 3, warp_n = wid >> 2;
    const int m0 = blockIdx.x * 128, n0 = blockIdx.y * 128;
    const uint32_t sb = smem_u32(smraw);
    const int kdim = KSTAGES * 16;

    const __half* Ah = (MODE == 0) ? g_Ah : g_Xh;
    const __half* Al = (MODE == 0) ? g_Al : g_Xl;    // unused loads skipped in MODE 0
    const __half* Bh = (MODE == 0) ? g_Bh + (size_t)layer * Hh * Hh : g_PBh;
    const __half* Bl = (MODE == 0) ? g_Bl + (size_t)layer * Hh * Hh : g_PBl;

    const int a_r = tid >> 1, a_c = tid & 1;
    const int b_r = tid >> 4, b_c = tid & 15;

#define LOAD_STAGE(slotbase, kt) do { \
        int k0 = (kt) * 16; \
        CPA((slotbase) + a_r * 48 + a_c * 16, \
            Ah + (size_t)(m0 + a_r) * kdim + k0 + a_c * 8); \
        if (MODE == 1) \
            CPA((slotbase) + ALO_O + a_r * 48 + a_c * 16, \
                Al + (size_t)(m0 + a_r) * kdim + k0 + a_c * 8); \
        CPA((slotbase) + BH_O + b_r * 272 + b_c * 16, \
            Bh + (size_t)(k0 + b_r) * Hh + n0 + b_c * 8); \
        CPA((slotbase) + BL_O + b_r * 272 + b_c * 16, \
            Bl + (size_t)(k0 + b_r) * Hh + n0 + b_c * 8); \
        asm volatile("cp.async.commit_group;" ::: "memory"); \
    } while (0)

    float acc[2][8][4];
    #pragma unroll
    for (int i = 0; i < 2; i++)
        #pragma unroll
        for (int j = 0; j < 8; j++)
            #pragma unroll
            for (int q = 0; q < 4; q++) acc[i][j][q] = 0.f;

    const uint32_t aoff = sb + (warp_m * 32 + (lane & 15)) * 48 + (lane >> 4) * 16;
    const uint32_t boff = sb + BH_O + (lane & 15) * 272 + (warp_n * 8 + (lane >> 4)) * 16;

    LOAD_STAGE(sb, 0);
    LOAD_STAGE(sb + SLOT, 1);
    LOAD_STAGE(sb + 2 * SLOT, 2);

    #pragma unroll
    for (int kt = 0; kt < KSTAGES; kt++) {
        const uint32_t s = (kt & 3) * SLOT;
        asm volatile("cp.async.wait_group 2;" ::: "memory");
        __syncthreads();
        if (kt + 3 < KSTAGES) {
            LOAD_STAGE(sb + ((kt + 3) & 3) * SLOT, kt + 3);
        } else {
            asm volatile("cp.async.commit_group;" ::: "memory");
        }

        uint32_t ah[2][4], al[2][4], bh[4][4], bl[4][4];
        #pragma unroll
        for (int mt = 0; mt < 2; mt++) {
            LDSM4(ah[mt], aoff + s + mt * 768);
            if (MODE == 1) LDSM4(al[mt], aoff + s + ALO_O + mt * 768);
        }
        #pragma unroll
        for (int nt = 0; nt < 4; nt++) {
            LDSM4T(bh[nt], boff + s + nt * 32);
            LDSM4T(bl[nt], boff + s + (BL_O - BH_O) + nt * 32);
        }
        #pragma unroll
        for (int mt = 0; mt < 2; mt++)
            #pragma unroll
            for (int nt = 0; nt < 4; nt++)
                #pragma unroll
                for (int nb = 0; nb < 2; nb++) {
                    float* c = acc[mt][nt * 2 + nb];
                    MMAF16(c, ah[mt], &bh[nt][nb * 2]);
                    MMAF16(c, ah[mt], &bl[nt][nb * 2]);
                    if (MODE == 1) MMAF16(c, al[mt], &bh[nt][nb * 2]);
                }
    }
#undef LOAD_STAGE

    #pragma unroll
    for (int mt = 0; mt < 2; mt++) {
        int rbase = m0 + warp_m * 32 + mt * 16 + (lane >> 2);
        #pragma unroll
        for (int half = 0; half < 2; half++) {
            int r = rbase + half * 8;
            #pragma unroll
            for (int j = 0; j < 8; j++) {
                int n = n0 + warp_n * 64 + j * 8 + (lane & 3) * 2;
                float vx = acc[mt][j][half * 2 + 0];
                float vy = acc[mt][j][half * 2 + 1];
                if (MODE == 0) {
                    __half2 hv = __floats2half2_rn(vx, vy);
                    *(__half2*)&g_hWh[(size_t)r * Hh + n] = hv;
                } else if (r < Nn) {
                    float2 bi = *(const float2*)&bias[n];
                    vx = fmaxf(vx + bi.x, 0.f);
                    vy = fmaxf(vy + bi.y, 0.f);
                    *(uint32_t*)&g_Ah[(size_t)r * Hh + n] = packh2(vx, vy);
                    *(uint32_t*)&g_Al[(size_t)r * Hh + n] = packl2(vx, vy);
                }
            }
        }
    }
}

// ---------------- SIMT SGEMM (head only) ----------------
__global__ void k_sgemm(const float* __restrict__ B, const float* __restrict__ bias,
                        int M, int N, int K, int sel) {
    const float* A = (sel == 2) ? g_pool : g_f1;
    float*       C = (sel == 2) ? g_f1  : g_f2;

    __shared__ float As[16][64];
    __shared__ float Bs[16][68];

    int tid = threadIdx.x;
    int m0 = blockIdx.y * 64, n0 = blockIdx.x * 64;
    int tr = tid >> 4, tc = tid & 15;
    int arow = tid >> 2, aq = (tid & 3) * 4;
    int brow = tid >> 4, bq = (tid & 15) * 4;

    float acc[4][4];
    #pragma unroll
    for (int i = 0; i < 4; i++)
        #pragma unroll
        for (int j = 0; j < 4; j++) acc[i][j] = 0.f;

    for (int k0 = 0; k0 < K; k0 += 16) {
        float4 av;
        if (m0 + arow < M)
            av = *reinterpret_cast<const float4*>(&A[(size_t)(m0 + arow) * K + k0 + aq]);
        else
            av = make_float4(0.f, 0.f, 0.f, 0.f);
        As[aq + 0][arow] = av.x;
        As[aq + 1][arow] = av.y;
        As[aq + 2][arow] = av.z;
        As[aq + 3][arow] = av.w;

        float4 bv = *reinterpret_cast<const float4*>(&B[(size_t)(k0 + brow) * N + n0 + bq]);
        Bs[brow][bq + 0] = bv.x;
        Bs[brow][bq + 1] = bv.y;
        Bs[brow][bq + 2] = bv.z;
        Bs[brow][bq + 3] = bv.w;
        __syncthreads();

        #pragma unroll
        for (int k = 0; k < 16; k++) {
            float arr[4], br[4];
            #pragma unroll
            for (int i = 0; i < 4; i++) arr[i] = As[k][tr * 4 + i];
            #pragma unroll
            for (int j = 0; j < 4; j++) br[j] = Bs[k][tc * 4 + j];
            #pragma unroll
            for (int i = 0; i < 4; i++)
                #pragma unroll
                for (int j = 0; j < 4; j++) acc[i][j] = fmaf(arr[i], br[j], acc[i][j]);
        }
        __syncthreads();
    }

    #pragma unroll
    for (int i = 0; i < 4; i++) {
        int m = m0 + tr * 4 + i;
        if (m >= M) continue;
        #pragma unroll
        for (int j = 0; j < 4; j++) {
            int n = n0 + tc * 4 + j;
            float v = fmaxf(acc[i][j] + bias[n], 0.f);
            C[(size_t)m * N + n] = v;
        }
    }
}

// ---------------- fused aggregation (champion loop) + fp16-pair residual ----------------
__global__ __launch_bounds__(256) void k_agg_fused(
        const float* __restrict__ bias, const float* __restrict__ gamma,
        const float* __restrict__ beta, const float* __restrict__ mean,
        const float* __restrict__ var) {
    int v = blockIdx.x * 4 + (threadIdx.x >> 6);
    if (v >= Nn) return;
    int c = (threadIdx.x & 63) * 4;

    float idv = g_isd[v];
    float ws = idv * idv;

    float4 acc;
    {
        uint2 sr = *(const uint2*)&g_hWh[(size_t)v * Hh + c];
        float2 s0 = __half22float2(*(__half2*)&sr.x);
        float2 s1 = __half22float2(*(__half2*)&sr.y);
        acc = make_float4(s0.x * ws, s0.y * ws, s1.x * ws, s1.y * ws);
    }

    int j = g_off[v], e = g_off[v + 1];
    for (; j + 4 <= e; j += 4) {
        int u0 = g_csr[j], u1 = g_csr[j + 1], u2 = g_csr[j + 2], u3 = g_csr[j + 3];
        float w0 = g_wgt[j], w1 = g_wgt[j + 1], w2 = g_wgt[j + 2], w3 = g_wgt[j + 3];
        uint2 q0 = *(const uint2*)&g_hWh[(size_t)u0 * Hh + c];
        uint2 q1 = *(const uint2*)&g_hWh[(size_t)u1 * Hh + c];
        uint2 q2 = *(const uint2*)&g_hWh[(size_t)u2 * Hh + c];
        uint2 q3 = *(const uint2*)&g_hWh[(size_t)u3 * Hh + c];
        fma4(acc, q0, w0);
        fma4(acc, q1, w1);
        fma4(acc, q2, w2);
        fma4(acc, q3, w3);
    }
    for (; j < e; j++) {
        int u = g_csr[j];
        float w = g_wgt[j];
        uint2 q = *(const uint2*)&g_hWh[(size_t)u * Hh + c];
        fma4(acc, q, w);
    }

    float4 bi = *(const float4*)&bias[c];
    float4 ga = *(const float4*)&gamma[c];
    float4 be = *(const float4*)&beta[c];
    float4 me = *(const float4*)&mean[c];
    float4 va = *(const float4*)&var[c];

    uint2 rh = *(const uint2*)&g_Ah[(size_t)v * Hh + c];
    uint2 rl = *(const uint2*)&g_Al[(size_t)v * Hh + c];
    float2 r01 = unpack2(rh.x, rl.x);
    float2 r23 = unpack2(rh.y, rl.y);

    float4 o;
    o.x = fmaxf((acc.x + bi.x - me.x) * (ga.x * rsqrtf(va.x + EPSc)) + be.x, 0.f) + r01.x;
    o.y = fmaxf((acc.y + bi.y - me.y) * (ga.y * rsqrtf(va.y + EPSc)) + be.y, 0.f) + r01.y;
    o.z = fmaxf((acc.z + bi.z - me.z) * (ga.z * rsqrtf(va.z + EPSc)) + be.z, 0.f) + r23.x;
    o.w = fmaxf((acc.w + bi.w - me.w) * (ga.w * rsqrtf(va.w + EPSc)) + be.w, 0.f) + r23.y;

    uint2 hv, lv;
    hv.x = packh2(o.x, o.y); hv.y = packh2(o.z, o.w);
    lv.x = packl2(o.x, o.y); lv.y = packl2(o.z, o.w);
    *(uint2*)&g_Ah[(size_t)v * Hh + c] = hv;
    *(uint2*)&g_Al[(size_t)v * Hh + c] = lv;
}

// ---------------- pooling: 2 graphs/block, 2 features/thread, packed loads ----------------
__global__ void k_pool(const int* __restrict__ batch) {
    __shared__ int sbb[3];
    int grp_base = blockIdx.x * 2;
    int sub = threadIdx.x >> 7;
    int t2 = (threadIdx.x & 127) * 2;
    if (threadIdx.x < 3) {
        int key = grp_base + threadIdx.x;
        int lo = 0, hi = Nn;
        while (lo < hi) {
            int mid = (lo + hi) >> 1;
            if (batch[mid] < key) lo = mid + 1; else hi = mid;
        }
        sbb[threadIdx.x] = lo;
    }
    __syncthreads();
    int grp = grp_base + sub;
    int s = sbb[sub], e = sbb[sub + 1];
    float2 sum = {0.f, 0.f}, mx = {-FLT_MAX, -FLT_MAX};
    for (int i = s; i < e; i++) {
        uint32_t hi = *(const uint32_t*)&g_Ah[(size_t)i * Hh + t2];
        uint32_t lo = *(const uint32_t*)&g_Al[(size_t)i * Hh + t2];
        float2 v = unpack2(hi, lo);
        sum.x += v.x; sum.y += v.y;
        mx.x = fmaxf(mx.x, v.x); mx.y = fmaxf(mx.y, v.y);
    }
    float cinv = 1.f / fmaxf((float)(e - s), 1.f);
    float* dst = &g_pool[(size_t)grp * (2 * Hh)];
    dst[t2]     = sum.x * cinv;
    dst[t2 + 1] = sum.y * cinv;
    dst[Hh + t2]     = mx.x;
    dst[Hh + t2 + 1] = mx.y;
}

// ---------------- final tiny GEMM ----------------
__global__ void k_head3(const float* __restrict__ W, const float* __restrict__ b,
                        float* __restrict__ out) {
    int idx = blockIdx.x * blockDim.x + threadIdx.x;
    if (idx >= Gg * Tt) return;
    int r = idx >> 2, c = idx & 3;
    float acc = b[c];
    const float* row = &g_f2[(size_t)r * 128];
    #pragma unroll 8
    for (int k = 0; k < 128; k++) acc = fmaf(row[k], W[k * 4 + c], acc);
    out[idx] = acc;
}

// ---------------- launch ----------------
extern "C" void kernel_launch(void* const* d_in, const int* in_sizes, int n_in,
                              void* d_out, int out_size) {
    const float* x     = (const float*)d_in[0];
    const int*   ei    = (const int*)d_in[1];
    const int*   batch = (const int*)d_in[2];
    const float* projW = (const float*)d_in[3];
    const float* projb = (const float*)d_in[4];
    const float* convW = (const float*)d_in[5];
    const float* convb = (const float*)d_in[6];
    const float* gamma = (const float*)d_in[7];
    const float* beta  = (const float*)d_in[8];
    const float* mean  = (const float*)d_in[9];
    const float* var   = (const float*)d_in[10];
    const float* W1 = (const float*)d_in[11];
    const float* b1 = (const float*)d_in[12];
    const float* W2 = (const float*)d_in[13];
    const float* b2 = (const float*)d_in[14];
    const float* W3 = (const float*)d_in[15];
    const float* b3 = (const float*)d_in[16];
    float* out = (float*)d_out;

    const int SCAN_B = (Nn + 1023) / 1024;
    const int SMEM_C = 4 * 14848;   // conv: 59392
    const int SMEM_P = 4 * 20992;   // proj: 83968

    cudaFuncSetAttribute(k_gemm_mma<16, 0>, cudaFuncAttributeMaxDynamicSharedMemorySize, SMEM_C);
    cudaFuncSetAttribute(k_gemm_mma<4, 1>, cudaFuncAttributeMaxDynamicSharedMemorySize, SMEM_P);

    // 0-2: splits + proj
    k_split_x  <<<(Nn * FIN / 4 + 255) / 256, 256>>>(x);
    k_wsplit   <<<(Ll * Hh * Hh + FIN * Hh + 255) / 256, 256>>>(convW, projW);
    k_gemm_mma<4, 1><<<dim3(MTILES, 2), 256, SMEM_P>>>(0, projb);

    // 3: conv GEMM layer 0 — in ncu window
    k_gemm_mma<16, 0><<<dim3(MTILES, 2), 256, SMEM_C>>>(0, nullptr);

    // CSR build
    k_count_edges<<<(Ee / 4 + 255) / 256, 256>>>(ei);
    k_scan_block <<<SCAN_B, 1024>>>();
    k_scan_add   <<<SCAN_B, 1024>>>();
    k_csr_fill   <<<(Ee / 4 + 255) / 256, 256>>>(ei);

    // layer 0 aggregation, then layers 1..3
    k_agg_fused<<<(Nn + 3) / 4, 256>>>(convb, gamma, beta, mean, var);
    for (int l = 1; l < Ll; l++) {
        k_gemm_mma<16, 0><<<dim3(MTILES, 2), 256, SMEM_C>>>(l, nullptr);
        k_agg_fused<<<(Nn + 3) / 4, 256>>>(convb + l * Hh, gamma + l * Hh, beta + l * Hh,
                                           mean + l * Hh, var + l * Hh);
    }

    // pooling + head
    k_pool<<<Gg / 2, 256>>>(batch);
    k_sgemm<<<dim3(Hh / 64, Gg / 64), 256>>>(W1, b1, Gg, Hh, 2 * Hh, 2);
    k_sgemm<<<dim3((Hh / 2) / 64, Gg / 64), 256>>>(W2, b2, Gg, Hh / 2, Hh, 3);
    k_head3<<<(Gg * Tt + 255) / 256, 256>>>(W3, b3, out);
}